// round 10
// baseline (speedup 1.0000x reference)
#include <cuda_runtime.h>
#include <cuda_bf16.h>
#include <math.h>
#include <stdint.h>

// ---------------- problem constants ----------------
#define BB        4
#define LSEQ      2048
#define DMODEL    1024
#define DIN       2048          // D_INNER
#define NH        32            // NHEADS
#define HD        64            // HEADDIM
#define DSTATE    128
#define CONVDIM   2304          // DIN + 2*DSTATE
#define DPROJ     4384          // 2*DIN + 2*DSTATE + NH
#define MROWS     (BB*LSEQ)     // 8192

typedef unsigned long long ull;

// ---------------- scratch (static __device__, no allocs) ----------------
__device__ float g_zxbcdt[(size_t)MROWS * DPROJ];
__device__ float g_xc[(size_t)MROWS * CONVDIM];
__device__ float g_y[(size_t)MROWS * DIN];
__device__ float g_dt[(size_t)MROWS * NH];
__device__ float g_dA[(size_t)MROWS * NH];

// bf16 split operands
__device__ __nv_bfloat16 g_ahi[(size_t)MROWS * DMODEL];
__device__ __nv_bfloat16 g_alo[(size_t)MROWS * DMODEL];
__device__ __nv_bfloat16 g_w1hi[(size_t)DPROJ * DMODEL];  // W_in^T  [N][K]
__device__ __nv_bfloat16 g_w1lo[(size_t)DPROJ * DMODEL];
__device__ __nv_bfloat16 g_yhi[(size_t)MROWS * DIN];
__device__ __nv_bfloat16 g_ylo[(size_t)MROWS * DIN];
__device__ __nv_bfloat16 g_w2hi[(size_t)DMODEL * DIN];    // W_out^T [N][K]
__device__ __nv_bfloat16 g_w2lo[(size_t)DMODEL * DIN];

// ---------------- f32x2 helpers ----------------
__device__ __forceinline__ ull ffma2(ull a, ull b, ull c) {
    ull d; asm("fma.rn.f32x2 %0, %1, %2, %3;" : "=l"(d) : "l"(a), "l"(b), "l"(c)); return d;
}
__device__ __forceinline__ ull fmul2(ull a, ull b) {
    ull d; asm("mul.rn.f32x2 %0, %1, %2;" : "=l"(d) : "l"(a), "l"(b)); return d;
}
__device__ __forceinline__ ull pack2(float lo, float hi) {
    ull r; asm("mov.b64 %0, {%1, %2};" : "=l"(r) : "f"(lo), "f"(hi)); return r;
}
__device__ __forceinline__ float2 unpack2(ull v) {
    float2 f; asm("mov.b64 {%0, %1}, %2;" : "=f"(f.x), "=f"(f.y) : "l"(v)); return f;
}

// ---------------- mma.sync / ldmatrix / cp.async helpers ----------------
__device__ __forceinline__ uint32_t smem_u32(const void* p) {
    uint32_t a;
    asm("{ .reg .u64 t; cvta.to.shared.u64 t, %1; cvt.u32.u64 %0, t; }" : "=r"(a) : "l"(p));
    return a;
}
__device__ __forceinline__ void ldsm4(uint32_t& r0, uint32_t& r1, uint32_t& r2, uint32_t& r3,
                                      uint32_t addr) {
    asm volatile("ldmatrix.sync.aligned.m8n8.x4.shared.b16 {%0,%1,%2,%3}, [%4];"
                 : "=r"(r0), "=r"(r1), "=r"(r2), "=r"(r3) : "r"(addr));
}
__device__ __forceinline__ void mma16816(float* c, uint32_t a0, uint32_t a1, uint32_t a2,
                                         uint32_t a3, uint32_t b0, uint32_t b1) {
    asm volatile(
        "mma.sync.aligned.m16n8k16.row.col.f32.bf16.bf16.f32 "
        "{%0,%1,%2,%3}, {%4,%5,%6,%7}, {%8,%9}, {%0,%1,%2,%3};"
        : "+f"(c[0]), "+f"(c[1]), "+f"(c[2]), "+f"(c[3])
        : "r"(a0), "r"(a1), "r"(a2), "r"(a3), "r"(b0), "r"(b1));
}
__device__ __forceinline__ void cp16(uint32_t saddr, const void* gaddr, uint32_t srcbytes) {
    asm volatile("cp.async.cg.shared.global [%0], [%1], 16, %2;"
                 :: "r"(saddr), "l"(gaddr), "r"(srcbytes));
}
__device__ __forceinline__ void cp4(uint32_t saddr, const void* gaddr) {
    asm volatile("cp.async.ca.shared.global [%0], [%1], 4;"
                 :: "r"(saddr), "l"(gaddr));
}
__device__ __forceinline__ void cp_commit() { asm volatile("cp.async.commit_group;"); }
template <int N_> __device__ __forceinline__ void cp_wait() {
    asm volatile("cp.async.wait_group %0;" :: "n"(N_));
}

// ---------------- split / transpose-split converters ----------------
__global__ void __launch_bounds__(256)
convert_split(const float* __restrict__ src, __nv_bfloat16* __restrict__ hi,
              __nv_bfloat16* __restrict__ lo, int n4)
{
    int i = blockIdx.x * 256 + threadIdx.x;
    if (i >= n4) return;
    float4 v = ((const float4*)src)[i];
    __nv_bfloat16 h0 = __float2bfloat16(v.x), h1 = __float2bfloat16(v.y);
    __nv_bfloat16 h2 = __float2bfloat16(v.z), h3 = __float2bfloat16(v.w);
    __nv_bfloat162 H0; H0.x = h0; H0.y = h1;
    __nv_bfloat162 H1; H1.x = h2; H1.y = h3;
    ((__nv_bfloat162*)hi)[i*2]   = H0;
    ((__nv_bfloat162*)hi)[i*2+1] = H1;
    __nv_bfloat162 L0, L1;
    L0.x = __float2bfloat16(v.x - __bfloat162float(h0));
    L0.y = __float2bfloat16(v.y - __bfloat162float(h1));
    L1.x = __float2bfloat16(v.z - __bfloat162float(h2));
    L1.y = __float2bfloat16(v.w - __bfloat162float(h3));
    ((__nv_bfloat162*)lo)[i*2]   = L0;
    ((__nv_bfloat162*)lo)[i*2+1] = L1;
}

// src [K][N] fp32 -> hiT/loT [N][K] bf16 split
__global__ void __launch_bounds__(256)
transpose_split(const float* __restrict__ src, __nv_bfloat16* __restrict__ hiT,
                __nv_bfloat16* __restrict__ loT, int K, int N)
{
    __shared__ float t[32][33];
    const int kb = blockIdx.y * 32, nb = blockIdx.x * 32;
    const int tx = threadIdx.x & 31, ty = threadIdx.x >> 5;
#pragma unroll
    for (int j = 0; j < 4; j++)
        t[ty + j*8][tx] = src[(size_t)(kb + ty + j*8) * N + nb + tx];
    __syncthreads();
#pragma unroll
    for (int j = 0; j < 4; j++) {
        const int n = nb + ty + j*8, k = kb + tx;
        const float v = t[tx][ty + j*8];
        const __nv_bfloat16 h = __float2bfloat16(v);
        hiT[(size_t)n * K + k] = h;
        loT[(size_t)n * K + k] = __float2bfloat16(v - __bfloat162float(h));
    }
}

// ---------------- HMMA GEMM: BK=16, 3-stage cp.async, 3 CTAs/SM --------------
// Stride 48B: ldmatrix start banks {0,12,24,4,16,28,8,20} = exact 32-bank
// partition, conflict-free. Stage = 4 tiles x 128 x 48B = 24KB; 3 stages = 72KB.
#define GS_STRIDE 48
#define GS_TILE   (128 * GS_STRIDE)   // 6144 B
#define GS_BUF    (4 * GS_TILE)       // 24576 B
#define GS_NSTAGE 3
#define GS_DYN    (GS_NSTAGE * GS_BUF)  // 73728 B

__global__ void __launch_bounds__(256, 3)
gemm_hmma(const __nv_bfloat16* __restrict__ Ahi, const __nv_bfloat16* __restrict__ Alo,
          const __nv_bfloat16* __restrict__ BhiT, const __nv_bfloat16* __restrict__ BloT,
          float* __restrict__ C, int N, int K)
{
    extern __shared__ char smem[];
    const uint32_t sb = smem_u32(smem);

    const int tid = threadIdx.x;
    const int lane = tid & 31;
    const int wid = tid >> 5;
    const int warp_m = wid & 1;
    const int warp_n = wid >> 1;
    const int rowBase = blockIdx.y << 7;
    const int colBase = blockIdx.x << 7;
    const int nkc = K >> 4;               // BK = 16

    float acc[4][4][4];
#pragma unroll
    for (int i = 0; i < 4; i++)
#pragma unroll
        for (int j = 0; j < 4; j++)
#pragma unroll
            for (int q = 0; q < 4; q++) acc[i][j][q] = 0.f;

    // chunk loader: 4 cp16 per thread (one per tile)
    const int lrow = tid >> 1, lc = tid & 1;      // 128 rows x 2 16B-cols
    const uint32_t lso = (uint32_t)(lrow * GS_STRIDE + lc * 16);
    const int bn = colBase + lrow;
    const int bnn = (bn < N) ? bn : 0;
    const uint32_t bvalid = (bn < N) ? 16u : 0u;

    auto load_chunk = [&](int kc, int slot) {
        const uint32_t base = sb + (uint32_t)slot * GS_BUF;
        const size_t ga = (size_t)(rowBase + lrow) * K + kc * 16 + lc * 8;
        const size_t gb = (size_t)bnn * K + kc * 16 + lc * 8;
        cp16(base + lso,               Ahi + ga, 16);
        cp16(base + GS_TILE + lso,     Alo + ga, 16);
        cp16(base + 2*GS_TILE + lso,   BhiT + gb, bvalid);
        cp16(base + 3*GS_TILE + lso,   BloT + gb, bvalid);
    };

    load_chunk(0, 0); cp_commit();
    load_chunk(1, 1); cp_commit();

    // fragment byte offset within a tile for this lane
    const uint32_t loff = (uint32_t)((lane & 15) * GS_STRIDE + (lane >> 4) * 16);

    int slot = 0;
    for (int kc = 0; kc < nkc; kc++) {
        cp_wait<1>();
        __syncthreads();

        const uint32_t base = sb + (uint32_t)slot * GS_BUF;
        const uint32_t aHb = base;
        const uint32_t aLb = base + GS_TILE;
        const uint32_t bHb = base + 2 * GS_TILE;
        const uint32_t bLb = base + 3 * GS_TILE;

        uint32_t aH[4][4], aL[4][4];
#pragma unroll
        for (int mt = 0; mt < 4; mt++) {
            const uint32_t ro = (uint32_t)((warp_m * 64 + mt * 16) * GS_STRIDE) + loff;
            ldsm4(aH[mt][0], aH[mt][1], aH[mt][2], aH[mt][3], aHb + ro);
            ldsm4(aL[mt][0], aL[mt][1], aL[mt][2], aL[mt][3], aLb + ro);
        }
        uint32_t bH[4][2], bL[4][2];
#pragma unroll
        for (int np = 0; np < 2; np++) {
            const uint32_t ro = (uint32_t)((warp_n * 32 + np * 16) * GS_STRIDE) + loff;
            uint32_t r0, r1, r2, r3;
            ldsm4(r0, r1, r2, r3, bHb + ro);
            bH[np*2][0] = r0; bH[np*2][1] = r2;
            bH[np*2+1][0] = r1; bH[np*2+1][1] = r3;
            ldsm4(r0, r1, r2, r3, bLb + ro);
            bL[np*2][0] = r0; bL[np*2][1] = r2;
            bL[np*2+1][0] = r1; bL[np*2+1][1] = r3;
        }
#pragma unroll
        for (int mt = 0; mt < 4; mt++)
#pragma unroll
            for (int nt = 0; nt < 4; nt++) {
                mma16816(acc[mt][nt], aH[mt][0], aH[mt][1], aH[mt][2], aH[mt][3],
                         bH[nt][0], bH[nt][1]);
                mma16816(acc[mt][nt], aH[mt][0], aH[mt][1], aH[mt][2], aH[mt][3],
                         bL[nt][0], bL[nt][1]);
                mma16816(acc[mt][nt], aL[mt][0], aL[mt][1], aL[mt][2], aL[mt][3],
                         bH[nt][0], bH[nt][1]);
            }

        __syncthreads();
        const int nx = kc + 2;
        if (nx < nkc) load_chunk(nx, (slot + 2) % GS_NSTAGE);
        cp_commit();
        slot = (slot + 1) % GS_NSTAGE;
    }

    const int g = lane >> 2, tg = lane & 3;
#pragma unroll
    for (int mt = 0; mt < 4; mt++) {
#pragma unroll
        for (int nt = 0; nt < 4; nt++) {
            const int col = colBase + warp_n * 32 + nt * 8 + tg * 2;
            if (col < N) {
                const int r0 = rowBase + warp_m * 64 + mt * 16 + g;
                float2 v0 = make_float2(acc[mt][nt][0], acc[mt][nt][1]);
                float2 v1 = make_float2(acc[mt][nt][2], acc[mt][nt][3]);
                *(float2*)(C + (size_t)r0 * N + col)       = v0;
                *(float2*)(C + (size_t)(r0 + 8) * N + col) = v1;
            }
        }
    }
}

// ---------------- conv(4) + SiLU: 8 timesteps per CTA (sliding window) -------
__global__ void __launch_bounds__(256)
conv_kernel(const float* __restrict__ conv_w, const float* __restrict__ conv_b)
{
    const int bl0 = blockIdx.x * 8;
    const int l0  = bl0 & (LSEQ - 1);
    const int tid = threadIdx.x;
    const float* base = g_zxbcdt + (size_t)bl0 * DPROJ + DIN;
    float* out = g_xc + (size_t)bl0 * CONVDIM;

    for (int c = tid; c < CONVDIM; c += 256) {
        const float4 w = *(const float4*)(conv_w + c * 4);
        const float bias = conv_b[c];
        float v[11];
#pragma unroll
        for (int k = 0; k < 11; k++) {
            const int ll = l0 + k - 3;
            v[k] = (ll >= 0) ? base[(ptrdiff_t)(k - 3) * DPROJ + c] : 0.f;
        }
#pragma unroll
        for (int j = 0; j < 8; j++) {
            const float a = bias + w.x * v[j] + w.y * v[j+1] + w.z * v[j+2] + w.w * v[j+3];
            out[(size_t)j * CONVDIM + c] = a / (1.f + expf(-a));
        }
    }
}

// ---------------- dt / dA ----------------
__global__ void __launch_bounds__(256)
dt_kernel(const float* __restrict__ dt_bias, const float* __restrict__ A_log)
{
    const int idx = blockIdx.x * 256 + threadIdx.x;
    const int bl = idx >> 5, hh = idx & 31;
    const float v = g_zxbcdt[(size_t)bl * DPROJ + (DPROJ - NH) + hh] + dt_bias[hh];
    const float dtv = (v > 20.f) ? v : log1pf(expf(v));
    g_dt[idx] = dtv;
    g_dA[idx] = expf(-expf(A_log[hh]) * dtv);
}

// ---------------- selective scan: 256 threads, 2p x 16n per thread ----------
#define SC_STAGES 4
#define SC_STEPS  4
__global__ void __launch_bounds__(256)
scan_kernel(const float* __restrict__ Dv)
{
    const int h = blockIdx.x, b = blockIdx.y;
    const int tid = threadIdx.x;
    const int nc = tid & 7;          // n-chunk (16 states)
    const int pg = tid >> 3;         // p-group (2 rows): p0 = 2*pg
    const int p0 = pg * 2;

    const float* xc  = g_xc + (size_t)b * LSEQ * CONVDIM;
    const float* dAp = g_dA + (size_t)b * LSEQ * NH + h;
    const float* dtp = g_dt + (size_t)b * LSEQ * NH + h;
    float* yout = g_y + (size_t)b * LSEQ * DIN + h * HD + p0;

    __shared__ __align__(16) float sB[SC_STAGES][SC_STEPS][160];
    __shared__ __align__(16) float sC[SC_STAGES][SC_STEPS][160];
    __shared__ __align__(16) float sx[SC_STAGES][SC_STEPS][64];
    __shared__ float sdA[SC_STAGES][SC_STEPS];
    __shared__ float sdt[SC_STAGES][SC_STEPS];

    auto load_stage = [&](int slot, int l0) {
#pragma unroll
        for (int pass = 0; pass < 2; pass++) {
            const int idx = tid + pass * 256;
            if (idx < 320) {
                const int j = idx / 80, op = idx % 80;
                const float* row = xc + (size_t)(l0 + j) * CONVDIM;
                if (op < 64) {
                    const int isC = op >> 5, o = op & 31;
                    const int chunk = o >> 2, q = o & 3;
                    const float* src = row + DIN + isC * DSTATE + chunk * 16 + q * 4;
                    float* dstf = (isC ? &sC[slot][j][0] : &sB[slot][j][0]) + chunk * 20 + q * 4;
                    cp16(smem_u32(dstf), src, 16);
                } else {
                    const int o = op - 64;
                    cp16(smem_u32(&sx[slot][j][o * 4]), row + h * HD + o * 4, 16);
                }
            } else if (idx < 328) {
                const int t = idx - 320, j = t >> 1;
                if (t & 1) cp4(smem_u32(&sdt[slot][j]), dtp + (size_t)(l0 + j) * NH);
                else       cp4(smem_u32(&sdA[slot][j]), dAp + (size_t)(l0 + j) * NH);
            }
        }
    };

    ull hs0[8], hs1[8];
#pragma unroll
    for (int i = 0; i < 8; i++) { hs0[i] = 0ull; hs1[i] = 0ull; }
    const float Dh = Dv[h];

#pragma unroll
    for (int s = 0; s < SC_STAGES; s++) { load_stage(s, SC_STEPS * s); cp_commit(); }

    const int niter = LSEQ / SC_STEPS;
    for (int it = 0; it < niter; it++) {
        const int slot = it & (SC_STAGES - 1);
        cp_wait<SC_STAGES - 1>();
        __syncthreads();

#pragma unroll
        for (int j = 0; j < SC_STEPS; j++) {
            const float dAv = sdA[slot][j];
            const float dtv = sdt[slot][j];
            const float2 xv = *(const float2*)&sx[slot][j][p0];
            const float s0 = dtv * xv.x, s1 = dtv * xv.y;
            const ull dA2 = pack2(dAv, dAv);
            const ull s20 = pack2(s0, s0);
            const ull s21 = pack2(s1, s1);

            const ulonglong2* B2 = (const ulonglong2*)(&sB[slot][j][nc * 20]);
            const ulonglong2* C2 = (const ulonglong2*)(&sC[slot][j][nc * 20]);
            ull acc0 = 0ull, acc1 = 0ull;
#pragma unroll
            for (int i = 0; i < 4; i++) {
                const ulonglong2 bb = B2[i], cc = C2[i];
                hs0[2*i]   = ffma2(dA2, hs0[2*i],   fmul2(s20, bb.x));
                acc0       = ffma2(hs0[2*i],   cc.x, acc0);
                hs1[2*i]   = ffma2(dA2, hs1[2*i],   fmul2(s21, bb.x));
                acc1       = ffma2(hs1[2*i],   cc.x, acc1);
                hs0[2*i+1] = ffma2(dA2, hs0[2*i+1], fmul2(s20, bb.y));
                acc0       = ffma2(hs0[2*i+1], cc.y, acc0);
                hs1[2*i+1] = ffma2(dA2, hs1[2*i+1], fmul2(s21, bb.y));
                acc1       = ffma2(hs1[2*i+1], cc.y, acc1);
            }
            const float2 f0 = unpack2(acc0), f1 = unpack2(acc1);
            float r0 = f0.x + f0.y;
            float r1 = f1.x + f1.y;
#pragma unroll
            for (int o = 1; o < 8; o <<= 1) {
                r0 += __shfl_xor_sync(0xffffffffu, r0, o);
                r1 += __shfl_xor_sync(0xffffffffu, r1, o);
            }
            if (nc == 0) {
                float2 ov;
                ov.x = r0 + Dh * xv.x;
                ov.y = r1 + Dh * xv.y;
                *(float2*)(yout + (size_t)(SC_STEPS * it + j) * DIN) = ov;
            }
        }
        __syncthreads();
        if (it + SC_STAGES < niter) load_stage(slot, SC_STEPS * (it + SC_STAGES));
        cp_commit();
    }
}

// ---------------- gating + RMSNorm -> bf16 hi/lo split ----------------
__global__ void __launch_bounds__(256)
gate_norm_kernel(const float* __restrict__ norm_w)
{
    const int bl = blockIdx.x;
    const float* yrow = g_y + (size_t)bl * DIN;
    const float* zrow = g_zxbcdt + (size_t)bl * DPROJ;
    __nv_bfloat16* hrow = g_yhi + (size_t)bl * DIN;
    __nv_bfloat16* lrow = g_ylo + (size_t)bl * DIN;
    const int tid = threadIdx.x;

    float v[8];
    float ss = 0.f;
#pragma unroll
    for (int j = 0; j < 8; j++) {
        const int c = tid + j * 256;
        const float z = zrow[c];
        const float val = yrow[c] * (z / (1.f + expf(-z)));
        v[j] = val;
        ss += val * val;
    }
#pragma unroll
    for (int o = 16; o; o >>= 1) ss += __shfl_xor_sync(0xffffffffu, ss, o);
    __shared__ float red[8];
    if ((tid & 31) == 0) red[tid >> 5] = ss;
    __syncthreads();
    float tot = 0.f;
#pragma unroll
    for (int i = 0; i < 8; i++) tot += red[i];
    const float scale = rsqrtf(tot * (1.f / (float)DIN) + 1e-5f);
#pragma unroll
    for (int j = 0; j < 8; j++) {
        const int c = tid + j * 256;
        const float o = v[j] * scale * norm_w[c];
        const __nv_bfloat16 hh = __float2bfloat16(o);
        hrow[c] = hh;
        lrow[c] = __float2bfloat16(o - __bfloat162float(hh));
    }
}

// ---------------- launch ----------------
extern "C" void kernel_launch(void* const* d_in, const int* in_sizes, int n_in,
                              void* d_out, int out_size)
{
    (void)in_sizes; (void)n_in; (void)out_size;

    const float* hidden  = (const float*)d_in[0];
    const float* W_in    = (const float*)d_in[1];
    const float* conv_w  = (const float*)d_in[2];
    const float* conv_b  = (const float*)d_in[3];
    const float* dt_bias = (const float*)d_in[4];
    const float* A_log   = (const float*)d_in[5];
    const float* Dvec    = (const float*)d_in[6];
    const float* norm_w  = (const float*)d_in[7];
    const float* W_out   = (const float*)d_in[8];
    float* out = (float*)d_out;

    static float* zx = nullptr;
    static __nv_bfloat16 *ahi, *alo, *w1hi, *w1lo, *yhi, *ylo, *w2hi, *w2lo;
    if (!zx) {
        void* p;
        cudaGetSymbolAddress(&p, g_zxbcdt); zx  = (float*)p;
        cudaGetSymbolAddress(&p, g_ahi);  ahi  = (__nv_bfloat16*)p;
        cudaGetSymbolAddress(&p, g_alo);  alo  = (__nv_bfloat16*)p;
        cudaGetSymbolAddress(&p, g_w1hi); w1hi = (__nv_bfloat16*)p;
        cudaGetSymbolAddress(&p, g_w1lo); w1lo = (__nv_bfloat16*)p;
        cudaGetSymbolAddress(&p, g_yhi);  yhi  = (__nv_bfloat16*)p;
        cudaGetSymbolAddress(&p, g_ylo);  ylo  = (__nv_bfloat16*)p;
        cudaGetSymbolAddress(&p, g_w2hi); w2hi = (__nv_bfloat16*)p;
        cudaGetSymbolAddress(&p, g_w2lo); w2lo = (__nv_bfloat16*)p;
        cudaFuncSetAttribute(gemm_hmma, cudaFuncAttributeMaxDynamicSharedMemorySize, GS_DYN);
    }

    // 0) operand prep
    {
        const int n4 = MROWS * DMODEL / 4;
        convert_split<<<(n4 + 255) / 256, 256>>>(hidden, ahi, alo, n4);
    }
    transpose_split<<<dim3(DPROJ / 32, DMODEL / 32), 256>>>(W_in, w1hi, w1lo, DMODEL, DPROJ);
    transpose_split<<<dim3(DMODEL / 32, DIN / 32), 256>>>(W_out, w2hi, w2lo, DIN, DMODEL);

    // 1) zxbcdt = hidden @ W_in
    gemm_hmma<<<dim3((DPROJ + 127) / 128, MROWS / 128), 256, GS_DYN>>>(
        ahi, alo, w1hi, w1lo, zx, DPROJ, DMODEL);

    // 2) conv + silu (8 steps/CTA) and dt/dA
    conv_kernel<<<MROWS / 8, 256>>>(conv_w, conv_b);
    dt_kernel<<<MROWS * NH / 256, 256>>>(dt_bias, A_log);

    // 3) selective scan (2p x 16n per thread)
    scan_kernel<<<dim3(NH, BB), 256>>>(Dvec);

    // 4) gating + rmsnorm -> bf16 hi/lo
    gate_norm_kernel<<<MROWS, 256>>>(norm_w);

    // 5) out = y @ W_out
    gemm_hmma<<<dim3(DMODEL / 128, MROWS / 128), 256, GS_DYN>>>(
        yhi, ylo, w2hi, w2lo, out, DMODEL, DIN);
}

// round 11
// speedup vs baseline: 2.2330x; 2.2330x over previous
#include <cuda_runtime.h>
#include <cuda_bf16.h>
#include <math.h>
#include <stdint.h>

// ---------------- problem constants ----------------
#define BB        4
#define LSEQ      2048
#define DMODEL    1024
#define DIN       2048          // D_INNER
#define NH        32            // NHEADS
#define HD        64            // HEADDIM
#define DSTATE    128
#define CONVDIM   2304          // DIN + 2*DSTATE
#define DPROJ     4384          // 2*DIN + 2*DSTATE + NH
#define MROWS     (BB*LSEQ)     // 8192

typedef unsigned long long ull;

// ---------------- scratch (static __device__, no allocs) ----------------
__device__ float g_zxbcdt[(size_t)MROWS * DPROJ];
__device__ float g_xc[(size_t)MROWS * CONVDIM];
__device__ float g_y[(size_t)MROWS * DIN];
__device__ float g_dt[(size_t)MROWS * NH];
__device__ float g_dA[(size_t)MROWS * NH];

// bf16 split operands
__device__ __nv_bfloat16 g_ahi[(size_t)MROWS * DMODEL];
__device__ __nv_bfloat16 g_alo[(size_t)MROWS * DMODEL];
__device__ __nv_bfloat16 g_w1hi[(size_t)DPROJ * DMODEL];  // W_in^T  [N][K]
__device__ __nv_bfloat16 g_w1lo[(size_t)DPROJ * DMODEL];
__device__ __nv_bfloat16 g_yhi[(size_t)MROWS * DIN];
__device__ __nv_bfloat16 g_ylo[(size_t)MROWS * DIN];
__device__ __nv_bfloat16 g_w2hi[(size_t)DMODEL * DIN];    // W_out^T [N][K]
__device__ __nv_bfloat16 g_w2lo[(size_t)DMODEL * DIN];

// ---------------- f32x2 helpers ----------------
__device__ __forceinline__ ull ffma2(ull a, ull b, ull c) {
    ull d; asm("fma.rn.f32x2 %0, %1, %2, %3;" : "=l"(d) : "l"(a), "l"(b), "l"(c)); return d;
}
__device__ __forceinline__ ull fmul2(ull a, ull b) {
    ull d; asm("mul.rn.f32x2 %0, %1, %2;" : "=l"(d) : "l"(a), "l"(b)); return d;
}
__device__ __forceinline__ ull pack2(float lo, float hi) {
    ull r; asm("mov.b64 %0, {%1, %2};" : "=l"(r) : "f"(lo), "f"(hi)); return r;
}
__device__ __forceinline__ float2 unpack2(ull v) {
    float2 f; asm("mov.b64 {%0, %1}, %2;" : "=f"(f.x), "=f"(f.y) : "l"(v)); return f;
}

// ---------------- mma.sync / ldmatrix / cp.async helpers ----------------
__device__ __forceinline__ uint32_t smem_u32(const void* p) {
    uint32_t a;
    asm("{ .reg .u64 t; cvta.to.shared.u64 t, %1; cvt.u32.u64 %0, t; }" : "=r"(a) : "l"(p));
    return a;
}
__device__ __forceinline__ void ldsm4(uint32_t& r0, uint32_t& r1, uint32_t& r2, uint32_t& r3,
                                      uint32_t addr) {
    asm volatile("ldmatrix.sync.aligned.m8n8.x4.shared.b16 {%0,%1,%2,%3}, [%4];"
                 : "=r"(r0), "=r"(r1), "=r"(r2), "=r"(r3) : "r"(addr));
}
__device__ __forceinline__ void mma16816(float* c, uint32_t a0, uint32_t a1, uint32_t a2,
                                         uint32_t a3, uint32_t b0, uint32_t b1) {
    asm volatile(
        "mma.sync.aligned.m16n8k16.row.col.f32.bf16.bf16.f32 "
        "{%0,%1,%2,%3}, {%4,%5,%6,%7}, {%8,%9}, {%0,%1,%2,%3};"
        : "+f"(c[0]), "+f"(c[1]), "+f"(c[2]), "+f"(c[3])
        : "r"(a0), "r"(a1), "r"(a2), "r"(a3), "r"(b0), "r"(b1));
}
__device__ __forceinline__ void cp16(uint32_t saddr, const void* gaddr, uint32_t srcbytes) {
    asm volatile("cp.async.cg.shared.global [%0], [%1], 16, %2;"
                 :: "r"(saddr), "l"(gaddr), "r"(srcbytes));
}
__device__ __forceinline__ void cp4(uint32_t saddr, const void* gaddr) {
    asm volatile("cp.async.ca.shared.global [%0], [%1], 4;"
                 :: "r"(saddr), "l"(gaddr));
}
__device__ __forceinline__ void cp_commit() { asm volatile("cp.async.commit_group;"); }
template <int N_> __device__ __forceinline__ void cp_wait() {
    asm volatile("cp.async.wait_group %0;" :: "n"(N_));
}

// ---------------- split / transpose-split converters ----------------
__global__ void __launch_bounds__(256)
convert_split(const float* __restrict__ src, __nv_bfloat16* __restrict__ hi,
              __nv_bfloat16* __restrict__ lo, int n4)
{
    int i = blockIdx.x * 256 + threadIdx.x;
    if (i >= n4) return;
    float4 v = ((const float4*)src)[i];
    __nv_bfloat16 h0 = __float2bfloat16(v.x), h1 = __float2bfloat16(v.y);
    __nv_bfloat16 h2 = __float2bfloat16(v.z), h3 = __float2bfloat16(v.w);
    __nv_bfloat162 H0; H0.x = h0; H0.y = h1;
    __nv_bfloat162 H1; H1.x = h2; H1.y = h3;
    ((__nv_bfloat162*)hi)[i*2]   = H0;
    ((__nv_bfloat162*)hi)[i*2+1] = H1;
    __nv_bfloat162 L0, L1;
    L0.x = __float2bfloat16(v.x - __bfloat162float(h0));
    L0.y = __float2bfloat16(v.y - __bfloat162float(h1));
    L1.x = __float2bfloat16(v.z - __bfloat162float(h2));
    L1.y = __float2bfloat16(v.w - __bfloat162float(h3));
    ((__nv_bfloat162*)lo)[i*2]   = L0;
    ((__nv_bfloat162*)lo)[i*2+1] = L1;
}

// src [K][N] fp32 -> hiT/loT [N][K] bf16 split
__global__ void __launch_bounds__(256)
transpose_split(const float* __restrict__ src, __nv_bfloat16* __restrict__ hiT,
                __nv_bfloat16* __restrict__ loT, int K, int N)
{
    __shared__ float t[32][33];
    const int kb = blockIdx.y * 32, nb = blockIdx.x * 32;
    const int tx = threadIdx.x & 31, ty = threadIdx.x >> 5;
#pragma unroll
    for (int j = 0; j < 4; j++)
        t[ty + j*8][tx] = src[(size_t)(kb + ty + j*8) * N + nb + tx];
    __syncthreads();
#pragma unroll
    for (int j = 0; j < 4; j++) {
        const int n = nb + ty + j*8, k = kb + tx;
        const float v = t[tx][ty + j*8];
        const __nv_bfloat16 h = __float2bfloat16(v);
        hiT[(size_t)n * K + k] = h;
        loT[(size_t)n * K + k] = __float2bfloat16(v - __bfloat162float(h));
    }
}

// ---------------- HMMA GEMM (REVERTED to R9 exact — measured 686us) ----------
#define GS_STRIDE 80
#define GS_TILE   (128 * GS_STRIDE)
#define GS_BUF    (4 * GS_TILE)
#define GS_DYN    (2 * GS_BUF)

__global__ void __launch_bounds__(256)
gemm_hmma(const __nv_bfloat16* __restrict__ Ahi, const __nv_bfloat16* __restrict__ Alo,
          const __nv_bfloat16* __restrict__ BhiT, const __nv_bfloat16* __restrict__ BloT,
          float* __restrict__ C, int N, int K)
{
    extern __shared__ char smem[];
    const uint32_t sb = smem_u32(smem);

    const int tid = threadIdx.x;
    const int lane = tid & 31;
    const int wid = tid >> 5;
    const int warp_m = wid & 1;
    const int warp_n = wid >> 1;
    const int rowBase = blockIdx.y << 7;
    const int colBase = blockIdx.x << 7;
    const int nkc = K >> 5;

    float acc[4][4][4];
#pragma unroll
    for (int i = 0; i < 4; i++)
#pragma unroll
        for (int j = 0; j < 4; j++)
#pragma unroll
            for (int q = 0; q < 4; q++) acc[i][j][q] = 0.f;

    auto load_chunk = [&](int kc, int buf) {
        const uint32_t base = sb + (uint32_t)buf * GS_BUF;
#pragma unroll
        for (int it = 0; it < 2; it++) {
            const int id = tid + it * 256;
            const int row = id >> 2, c = id & 3;
            const size_t g = (size_t)(rowBase + row) * K + kc * 32 + c * 8;
            const uint32_t so = (uint32_t)(row * GS_STRIDE + c * 16);
            cp16(base + so,            Ahi + g, 16);
            cp16(base + GS_TILE + so,  Alo + g, 16);
        }
#pragma unroll
        for (int it = 0; it < 2; it++) {
            const int id = tid + it * 256;
            const int row = id >> 2, c = id & 3;
            const int n = colBase + row;
            const int nn = (n < N) ? n : 0;
            const uint32_t valid = (n < N) ? 16u : 0u;
            const size_t g = (size_t)nn * K + kc * 32 + c * 8;
            const uint32_t so = (uint32_t)(row * GS_STRIDE + c * 16);
            cp16(base + 2*GS_TILE + so, BhiT + g, valid);
            cp16(base + 3*GS_TILE + so, BloT + g, valid);
        }
    };

    load_chunk(0, 0);
    cp_commit();

    for (int kc = 0; kc < nkc; kc++) {
        const int buf = kc & 1;
        if (kc + 1 < nkc) {
            load_chunk(kc + 1, buf ^ 1);
            cp_commit();
            cp_wait<1>();
        } else {
            cp_wait<0>();
        }
        __syncthreads();

        const uint32_t base = sb + (uint32_t)buf * GS_BUF;
        const uint32_t aHb = base;
        const uint32_t aLb = base + GS_TILE;
        const uint32_t bHb = base + 2 * GS_TILE;
        const uint32_t bLb = base + 3 * GS_TILE;

#pragma unroll
        for (int ks = 0; ks < 2; ks++) {
            const int kb = ks * 16;
            const uint32_t loff = (uint32_t)((lane & 15) * GS_STRIDE + kb * 2 + (lane >> 4) * 16);

            uint32_t aH[4][4], aL[4][4];
#pragma unroll
            for (int mt = 0; mt < 4; mt++) {
                const uint32_t ro = (uint32_t)((warp_m * 64 + mt * 16) * GS_STRIDE) + loff;
                ldsm4(aH[mt][0], aH[mt][1], aH[mt][2], aH[mt][3], aHb + ro);
                ldsm4(aL[mt][0], aL[mt][1], aL[mt][2], aL[mt][3], aLb + ro);
            }
            uint32_t bH[4][2], bL[4][2];
#pragma unroll
            for (int np = 0; np < 2; np++) {
                const uint32_t ro = (uint32_t)((warp_n * 32 + np * 16) * GS_STRIDE) + loff;
                uint32_t r0, r1, r2, r3;
                ldsm4(r0, r1, r2, r3, bHb + ro);
                bH[np*2][0] = r0; bH[np*2][1] = r2;
                bH[np*2+1][0] = r1; bH[np*2+1][1] = r3;
                ldsm4(r0, r1, r2, r3, bLb + ro);
                bL[np*2][0] = r0; bL[np*2][1] = r2;
                bL[np*2+1][0] = r1; bL[np*2+1][1] = r3;
            }
#pragma unroll
            for (int mt = 0; mt < 4; mt++)
#pragma unroll
                for (int nt = 0; nt < 4; nt++) {
                    mma16816(acc[mt][nt], aH[mt][0], aH[mt][1], aH[mt][2], aH[mt][3],
                             bH[nt][0], bH[nt][1]);
                    mma16816(acc[mt][nt], aH[mt][0], aH[mt][1], aH[mt][2], aH[mt][3],
                             bL[nt][0], bL[nt][1]);
                    mma16816(acc[mt][nt], aL[mt][0], aL[mt][1], aL[mt][2], aL[mt][3],
                             bH[nt][0], bH[nt][1]);
                }
        }
        __syncthreads();
    }

    const int g = lane >> 2, tg = lane & 3;
#pragma unroll
    for (int mt = 0; mt < 4; mt++) {
#pragma unroll
        for (int nt = 0; nt < 4; nt++) {
            const int col = colBase + warp_n * 32 + nt * 8 + tg * 2;
            if (col < N) {
                const int r0 = rowBase + warp_m * 64 + mt * 16 + g;
                float2 v0 = make_float2(acc[mt][nt][0], acc[mt][nt][1]);
                float2 v1 = make_float2(acc[mt][nt][2], acc[mt][nt][3]);
                *(float2*)(C + (size_t)r0 * N + col)       = v0;
                *(float2*)(C + (size_t)(r0 + 8) * N + col) = v1;
            }
        }
    }
}

// ---------------- conv(4) + SiLU: 8 timesteps per CTA (sliding window) -------
__global__ void __launch_bounds__(256)
conv_kernel(const float* __restrict__ conv_w, const float* __restrict__ conv_b)
{
    const int bl0 = blockIdx.x * 8;
    const int l0  = bl0 & (LSEQ - 1);
    const int tid = threadIdx.x;
    const float* base = g_zxbcdt + (size_t)bl0 * DPROJ + DIN;
    float* out = g_xc + (size_t)bl0 * CONVDIM;

    for (int c = tid; c < CONVDIM; c += 256) {
        const float4 w = *(const float4*)(conv_w + c * 4);
        const float bias = conv_b[c];
        float v[11];
#pragma unroll
        for (int k = 0; k < 11; k++) {
            const int ll = l0 + k - 3;
            v[k] = (ll >= 0) ? base[(ptrdiff_t)(k - 3) * DPROJ + c] : 0.f;
        }
#pragma unroll
        for (int j = 0; j < 8; j++) {
            const float a = bias + w.x * v[j] + w.y * v[j+1] + w.z * v[j+2] + w.w * v[j+3];
            out[(size_t)j * CONVDIM + c] = a / (1.f + expf(-a));
        }
    }
}

// ---------------- dt / dA ----------------
__global__ void __launch_bounds__(256)
dt_kernel(const float* __restrict__ dt_bias, const float* __restrict__ A_log)
{
    const int idx = blockIdx.x * 256 + threadIdx.x;
    const int bl = idx >> 5, hh = idx & 31;
    const float v = g_zxbcdt[(size_t)bl * DPROJ + (DPROJ - NH) + hh] + dt_bias[hh];
    const float dtv = (v > 20.f) ? v : log1pf(expf(v));
    g_dt[idx] = dtv;
    g_dA[idx] = expf(-expf(A_log[hh]) * dtv);
}

// ---------------- selective scan: p-split, 2 CTAs per (b,h) -----------------
// blockIdx.z = p-half (32 rows). 256 threads: nc = tid&7 (16 n-states),
// pg = tid>>3 (0..31) -> p = pz*32 + pg. 2 CTAs co-resident per SM hide each
// other's barrier/load latency (R9 scan ran 2.6x above its fma floor at 1 CTA/SM).
#define SC_STAGES 4
#define SC_STEPS  4
__global__ void __launch_bounds__(256)
scan_kernel(const float* __restrict__ Dv)
{
    const int h = blockIdx.x, b = blockIdx.y, pz = blockIdx.z;
    const int tid = threadIdx.x;
    const int nc = tid & 7;
    const int pg = tid >> 3;
    const int p  = pz * 32 + pg;

    const float* xc  = g_xc + (size_t)b * LSEQ * CONVDIM;
    const float* dAp = g_dA + (size_t)b * LSEQ * NH + h;
    const float* dtp = g_dt + (size_t)b * LSEQ * NH + h;
    float* yout = g_y + (size_t)b * LSEQ * DIN + h * HD + p;

    __shared__ __align__(16) float sB[SC_STAGES][SC_STEPS][160];
    __shared__ __align__(16) float sC[SC_STAGES][SC_STEPS][160];
    __shared__ __align__(16) float sx[SC_STAGES][SC_STEPS][32];
    __shared__ float sdA[SC_STAGES][SC_STEPS];
    __shared__ float sdt[SC_STAGES][SC_STEPS];

    // per step: 72 cp16 (B 32, C 32, x 8) + 2 cp4 = 74 ops; 4 steps = 296.
    auto load_stage = [&](int slot, int l0) {
#pragma unroll
        for (int pass = 0; pass < 2; pass++) {
            const int idx = tid + pass * 256;
            if (idx < 288) {
                const int j = idx / 72, op = idx % 72;
                const float* row = xc + (size_t)(l0 + j) * CONVDIM;
                if (op < 64) {
                    const int isC = op >> 5, o = op & 31;
                    const int chunk = o >> 2, q = o & 3;
                    const float* src = row + DIN + isC * DSTATE + chunk * 16 + q * 4;
                    float* dstf = (isC ? &sC[slot][j][0] : &sB[slot][j][0]) + chunk * 20 + q * 4;
                    cp16(smem_u32(dstf), src, 16);
                } else {
                    const int o = op - 64;
                    cp16(smem_u32(&sx[slot][j][o * 4]), row + h * HD + pz * 32 + o * 4, 16);
                }
            } else if (idx < 296) {
                const int t = idx - 288, j = t >> 1;
                if (t & 1) cp4(smem_u32(&sdt[slot][j]), dtp + (size_t)(l0 + j) * NH);
                else       cp4(smem_u32(&sdA[slot][j]), dAp + (size_t)(l0 + j) * NH);
            }
        }
    };

    ull hs[8];
#pragma unroll
    for (int i = 0; i < 8; i++) hs[i] = 0ull;
    const float Dh = Dv[h];

#pragma unroll
    for (int s = 0; s < SC_STAGES; s++) { load_stage(s, SC_STEPS * s); cp_commit(); }

    const int niter = LSEQ / SC_STEPS;
    for (int it = 0; it < niter; it++) {
        const int slot = it & (SC_STAGES - 1);
        cp_wait<SC_STAGES - 1>();
        __syncthreads();

#pragma unroll
        for (int j = 0; j < SC_STEPS; j++) {
            const float dAv = sdA[slot][j];
            const float dtv = sdt[slot][j];
            const float xv  = sx[slot][j][pg];
            const float sv  = dtv * xv;
            const ull dA2 = pack2(dAv, dAv);
            const ull s2  = pack2(sv, sv);

            const ulonglong2* B2 = (const ulonglong2*)(&sB[slot][j][nc * 20]);
            const ulonglong2* C2 = (const ulonglong2*)(&sC[slot][j][nc * 20]);
            ull acc0 = 0ull, acc1 = 0ull;
#pragma unroll
            for (int i = 0; i < 4; i++) {
                const ulonglong2 bb = B2[i], cc = C2[i];
                hs[2*i]   = ffma2(dA2, hs[2*i],   fmul2(s2, bb.x));
                acc0      = ffma2(hs[2*i],   cc.x, acc0);
                hs[2*i+1] = ffma2(dA2, hs[2*i+1], fmul2(s2, bb.y));
                acc1      = ffma2(hs[2*i+1], cc.y, acc1);
            }
            const float2 f0 = unpack2(acc0), f1 = unpack2(acc1);
            float r = (f0.x + f0.y) + (f1.x + f1.y);
            r += __shfl_xor_sync(0xffffffffu, r, 1);
            r += __shfl_xor_sync(0xffffffffu, r, 2);
            r += __shfl_xor_sync(0xffffffffu, r, 4);
            if (nc == 0) yout[(size_t)(SC_STEPS * it + j) * DIN] = r + Dh * xv;
        }
        __syncthreads();
        if (it + SC_STAGES < niter) load_stage(slot, SC_STEPS * (it + SC_STAGES));
        cp_commit();
    }
}

// ---------------- gating + RMSNorm -> bf16 hi/lo split ----------------
__global__ void __launch_bounds__(256)
gate_norm_kernel(const float* __restrict__ norm_w)
{
    const int bl = blockIdx.x;
    const float* yrow = g_y + (size_t)bl * DIN;
    const float* zrow = g_zxbcdt + (size_t)bl * DPROJ;
    __nv_bfloat16* hrow = g_yhi + (size_t)bl * DIN;
    __nv_bfloat16* lrow = g_ylo + (size_t)bl * DIN;
    const int tid = threadIdx.x;

    float v[8];
    float ss = 0.f;
#pragma unroll
    for (int j = 0; j < 8; j++) {
        const int c = tid + j * 256;
        const float z = zrow[c];
        const float val = yrow[c] * (z / (1.f + expf(-z)));
        v[j] = val;
        ss += val * val;
    }
#pragma unroll
    for (int o = 16; o; o >>= 1) ss += __shfl_xor_sync(0xffffffffu, ss, o);
    __shared__ float red[8];
    if ((tid & 31) == 0) red[tid >> 5] = ss;
    __syncthreads();
    float tot = 0.f;
#pragma unroll
    for (int i = 0; i < 8; i++) tot += red[i];
    const float scale = rsqrtf(tot * (1.f / (float)DIN) + 1e-5f);
#pragma unroll
    for (int j = 0; j < 8; j++) {
        const int c = tid + j * 256;
        const float o = v[j] * scale * norm_w[c];
        const __nv_bfloat16 hh = __float2bfloat16(o);
        hrow[c] = hh;
        lrow[c] = __float2bfloat16(o - __bfloat162float(hh));
    }
}

// ---------------- launch ----------------
extern "C" void kernel_launch(void* const* d_in, const int* in_sizes, int n_in,
                              void* d_out, int out_size)
{
    (void)in_sizes; (void)n_in; (void)out_size;

    const float* hidden  = (const float*)d_in[0];
    const float* W_in    = (const float*)d_in[1];
    const float* conv_w  = (const float*)d_in[2];
    const float* conv_b  = (const float*)d_in[3];
    const float* dt_bias = (const float*)d_in[4];
    const float* A_log   = (const float*)d_in[5];
    const float* Dvec    = (const float*)d_in[6];
    const float* norm_w  = (const float*)d_in[7];
    const float* W_out   = (const float*)d_in[8];
    float* out = (float*)d_out;

    static float* zx = nullptr;
    static __nv_bfloat16 *ahi, *alo, *w1hi, *w1lo, *yhi, *ylo, *w2hi, *w2lo;
    if (!zx) {
        void* p;
        cudaGetSymbolAddress(&p, g_zxbcdt); zx  = (float*)p;
        cudaGetSymbolAddress(&p, g_ahi);  ahi  = (__nv_bfloat16*)p;
        cudaGetSymbolAddress(&p, g_alo);  alo  = (__nv_bfloat16*)p;
        cudaGetSymbolAddress(&p, g_w1hi); w1hi = (__nv_bfloat16*)p;
        cudaGetSymbolAddress(&p, g_w1lo); w1lo = (__nv_bfloat16*)p;
        cudaGetSymbolAddress(&p, g_yhi);  yhi  = (__nv_bfloat16*)p;
        cudaGetSymbolAddress(&p, g_ylo);  ylo  = (__nv_bfloat16*)p;
        cudaGetSymbolAddress(&p, g_w2hi); w2hi = (__nv_bfloat16*)p;
        cudaGetSymbolAddress(&p, g_w2lo); w2lo = (__nv_bfloat16*)p;
        cudaFuncSetAttribute(gemm_hmma, cudaFuncAttributeMaxDynamicSharedMemorySize, GS_DYN);
    }

    // 0) operand prep
    {
        const int n4 = MROWS * DMODEL / 4;
        convert_split<<<(n4 + 255) / 256, 256>>>(hidden, ahi, alo, n4);
    }
    transpose_split<<<dim3(DPROJ / 32, DMODEL / 32), 256>>>(W_in, w1hi, w1lo, DMODEL, DPROJ);
    transpose_split<<<dim3(DMODEL / 32, DIN / 32), 256>>>(W_out, w2hi, w2lo, DIN, DMODEL);

    // 1) zxbcdt = hidden @ W_in
    gemm_hmma<<<dim3((DPROJ + 127) / 128, MROWS / 128), 256, GS_DYN>>>(
        ahi, alo, w1hi, w1lo, zx, DPROJ, DMODEL);

    // 2) conv + silu (8 steps/CTA) and dt/dA
    conv_kernel<<<MROWS / 8, 256>>>(conv_w, conv_b);
    dt_kernel<<<MROWS * NH / 256, 256>>>(dt_bias, A_log);

    // 3) selective scan (p-split: 2 CTAs per (b,h), 2 resident/SM)
    scan_kernel<<<dim3(NH, BB, 2), 256>>>(Dvec);

    // 4) gating + rmsnorm -> bf16 hi/lo
    gate_norm_kernel<<<MROWS, 256>>>(norm_w);

    // 5) out = y @ W_out
    gemm_hmma<<<dim3(DMODEL / 128, MROWS / 128), 256, GS_DYN>>>(
        yhi, ylo, w2hi, w2lo, out, DMODEL, DIN);
}

// round 12
// speedup vs baseline: 4.1623x; 1.8641x over previous
#include <cuda_runtime.h>
#include <cuda_fp16.h>
#include <cuda_bf16.h>
#include <math.h>
#include <stdint.h>

// ---------------- problem constants ----------------
#define BB        4
#define LSEQ      2048
#define DMODEL    1024
#define DIN       2048          // D_INNER
#define NH        32            // NHEADS
#define HD        64            // HEADDIM
#define DSTATE    128
#define CONVDIM   2304          // DIN + 2*DSTATE
#define DPROJ     4384          // 2*DIN + 2*DSTATE + NH
#define MROWS     (BB*LSEQ)     // 8192

typedef unsigned long long ull;

// ---------------- scratch (static __device__, no allocs) ----------------
__device__ float g_zxbcdt[(size_t)MROWS * DPROJ];
__device__ float g_xc[(size_t)MROWS * CONVDIM];
__device__ float g_y[(size_t)MROWS * DIN];
__device__ float g_dt[(size_t)MROWS * NH];
__device__ float g_dA[(size_t)MROWS * NH];

// fp16 operands (single precision pass)
__device__ __half g_ah[(size_t)MROWS * DMODEL];     // hidden fp16
__device__ __half g_w1h[(size_t)DPROJ * DMODEL];    // W_in^T  [N][K]
__device__ __half g_yh[(size_t)MROWS * DIN];        // gated/normed y
__device__ __half g_w2h[(size_t)DMODEL * DIN];      // W_out^T [N][K]

// ---------------- f32x2 helpers ----------------
__device__ __forceinline__ ull ffma2(ull a, ull b, ull c) {
    ull d; asm("fma.rn.f32x2 %0, %1, %2, %3;" : "=l"(d) : "l"(a), "l"(b), "l"(c)); return d;
}
__device__ __forceinline__ ull fmul2(ull a, ull b) {
    ull d; asm("mul.rn.f32x2 %0, %1, %2;" : "=l"(d) : "l"(a), "l"(b)); return d;
}
__device__ __forceinline__ ull pack2(float lo, float hi) {
    ull r; asm("mov.b64 %0, {%1, %2};" : "=l"(r) : "f"(lo), "f"(hi)); return r;
}
__device__ __forceinline__ float2 unpack2(ull v) {
    float2 f; asm("mov.b64 {%0, %1}, %2;" : "=f"(f.x), "=f"(f.y) : "l"(v)); return f;
}

// ---------------- mma.sync / ldmatrix / cp.async helpers ----------------
__device__ __forceinline__ uint32_t smem_u32(const void* p) {
    uint32_t a;
    asm("{ .reg .u64 t; cvta.to.shared.u64 t, %1; cvt.u32.u64 %0, t; }" : "=r"(a) : "l"(p));
    return a;
}
__device__ __forceinline__ void ldsm4(uint32_t& r0, uint32_t& r1, uint32_t& r2, uint32_t& r3,
                                      uint32_t addr) {
    asm volatile("ldmatrix.sync.aligned.m8n8.x4.shared.b16 {%0,%1,%2,%3}, [%4];"
                 : "=r"(r0), "=r"(r1), "=r"(r2), "=r"(r3) : "r"(addr));
}
__device__ __forceinline__ void mma16816h(float* c, uint32_t a0, uint32_t a1, uint32_t a2,
                                          uint32_t a3, uint32_t b0, uint32_t b1) {
    asm volatile(
        "mma.sync.aligned.m16n8k16.row.col.f32.f16.f16.f32 "
        "{%0,%1,%2,%3}, {%4,%5,%6,%7}, {%8,%9}, {%0,%1,%2,%3};"
        : "+f"(c[0]), "+f"(c[1]), "+f"(c[2]), "+f"(c[3])
        : "r"(a0), "r"(a1), "r"(a2), "r"(a3), "r"(b0), "r"(b1));
}
__device__ __forceinline__ void cp16(uint32_t saddr, const void* gaddr, uint32_t srcbytes) {
    asm volatile("cp.async.cg.shared.global [%0], [%1], 16, %2;"
                 :: "r"(saddr), "l"(gaddr), "r"(srcbytes));
}
__device__ __forceinline__ void cp4(uint32_t saddr, const void* gaddr) {
    asm volatile("cp.async.ca.shared.global [%0], [%1], 4;"
                 :: "r"(saddr), "l"(gaddr));
}
__device__ __forceinline__ void cp_commit() { asm volatile("cp.async.commit_group;"); }
template <int N_> __device__ __forceinline__ void cp_wait() {
    asm volatile("cp.async.wait_group %0;" :: "n"(N_));
}

// ---------------- converters (fp32 -> fp16) ----------------
__global__ void __launch_bounds__(256)
convert_h(const float* __restrict__ src, __half* __restrict__ dst, int n4)
{
    int i = blockIdx.x * 256 + threadIdx.x;
    if (i >= n4) return;
    float4 v = ((const float4*)src)[i];
    __half2 h0; h0.x = __float2half(v.x); h0.y = __float2half(v.y);
    __half2 h1; h1.x = __float2half(v.z); h1.y = __float2half(v.w);
    ((__half2*)dst)[i*2]   = h0;
    ((__half2*)dst)[i*2+1] = h1;
}

// src [K][N] fp32 -> dstT [N][K] fp16
__global__ void __launch_bounds__(256)
transpose_h(const float* __restrict__ src, __half* __restrict__ dstT, int K, int N)
{
    __shared__ float t[32][33];
    const int kb = blockIdx.y * 32, nb = blockIdx.x * 32;
    const int tx = threadIdx.x & 31, ty = threadIdx.x >> 5;
#pragma unroll
    for (int j = 0; j < 4; j++)
        t[ty + j*8][tx] = src[(size_t)(kb + ty + j*8) * N + nb + tx];
    __syncthreads();
#pragma unroll
    for (int j = 0; j < 4; j++) {
        const int n = nb + ty + j*8, k = kb + tx;
        dstT[(size_t)n * K + k] = __float2half(t[tx][ty + j*8]);
    }
}

// ---------------- HMMA GEMM: fp16 single-pass, BK=64, 2-stage cp.async -------
// Stride 144B: ldmatrix phase banks {4r..4r+3} -> conflict-free.
// Per chunk per warp: 24 ldsm4 + 64 mma between barriers; 16/32 chunks total.
#define GS_STRIDE 144
#define GS_TILE   (128 * GS_STRIDE)   // 18432 B
#define GS_BUF    (2 * GS_TILE)       // A|B = 36864 B
#define GS_DYN    (2 * GS_BUF)        // 73728 B

__global__ void __launch_bounds__(256)
gemm_hmma(const __half* __restrict__ A, const __half* __restrict__ BT,
          float* __restrict__ C, int N, int K)
{
    extern __shared__ char smem[];
    const uint32_t sb = smem_u32(smem);

    const int tid = threadIdx.x;
    const int lane = tid & 31;
    const int wid = tid >> 5;
    const int warp_m = wid & 1;
    const int warp_n = wid >> 1;
    const int rowBase = blockIdx.y << 7;
    const int colBase = blockIdx.x << 7;
    const int nkc = K >> 6;               // BK = 64

    float acc[4][4][4];
#pragma unroll
    for (int i = 0; i < 4; i++)
#pragma unroll
        for (int j = 0; j < 4; j++)
#pragma unroll
            for (int q = 0; q < 4; q++) acc[i][j][q] = 0.f;

    // loader: A tile 128 x 64 fp16 (8 c16/row), B same. 4 passes each.
    auto load_chunk = [&](int kc, int buf) {
        const uint32_t base = sb + (uint32_t)buf * GS_BUF;
#pragma unroll
        for (int it = 0; it < 4; it++) {
            const int id = tid + it * 256;
            const int row = id >> 3, c = id & 7;
            const size_t g = (size_t)(rowBase + row) * K + kc * 64 + c * 8;
            cp16(base + (uint32_t)(row * GS_STRIDE + c * 16), A + g, 16);
        }
#pragma unroll
        for (int it = 0; it < 4; it++) {
            const int id = tid + it * 256;
            const int row = id >> 3, c = id & 7;
            const int n = colBase + row;
            const int nn = (n < N) ? n : 0;
            const uint32_t valid = (n < N) ? 16u : 0u;
            const size_t g = (size_t)nn * K + kc * 64 + c * 8;
            cp16(base + GS_TILE + (uint32_t)(row * GS_STRIDE + c * 16), BT + g, valid);
        }
    };

    load_chunk(0, 0);
    cp_commit();

    for (int kc = 0; kc < nkc; kc++) {
        const int buf = kc & 1;
        if (kc + 1 < nkc) {
            load_chunk(kc + 1, buf ^ 1);
            cp_commit();
            cp_wait<1>();
        } else {
            cp_wait<0>();
        }
        __syncthreads();

        const uint32_t aTb = sb + (uint32_t)buf * GS_BUF;
        const uint32_t bTb = aTb + GS_TILE;

#pragma unroll
        for (int ks = 0; ks < 4; ks++) {
            const uint32_t loff = (uint32_t)((lane & 15) * GS_STRIDE + (lane >> 4) * 16 + ks * 32);

            uint32_t aH[4][4];
#pragma unroll
            for (int mt = 0; mt < 4; mt++) {
                const uint32_t ro = (uint32_t)((warp_m * 64 + mt * 16) * GS_STRIDE) + loff;
                ldsm4(aH[mt][0], aH[mt][1], aH[mt][2], aH[mt][3], aTb + ro);
            }
            uint32_t bH[4][2];
#pragma unroll
            for (int np = 0; np < 2; np++) {
                const uint32_t ro = (uint32_t)((warp_n * 32 + np * 16) * GS_STRIDE) + loff;
                uint32_t r0, r1, r2, r3;
                ldsm4(r0, r1, r2, r3, bTb + ro);
                bH[np*2][0] = r0; bH[np*2][1] = r2;
                bH[np*2+1][0] = r1; bH[np*2+1][1] = r3;
            }
#pragma unroll
            for (int mt = 0; mt < 4; mt++)
#pragma unroll
                for (int nt = 0; nt < 4; nt++)
                    mma16816h(acc[mt][nt], aH[mt][0], aH[mt][1], aH[mt][2], aH[mt][3],
                              bH[nt][0], bH[nt][1]);
        }
        __syncthreads();
    }

    const int g = lane >> 2, tg = lane & 3;
#pragma unroll
    for (int mt = 0; mt < 4; mt++) {
#pragma unroll
        for (int nt = 0; nt < 4; nt++) {
            const int col = colBase + warp_n * 32 + nt * 8 + tg * 2;
            if (col < N) {
                const int r0 = rowBase + warp_m * 64 + mt * 16 + g;
                float2 v0 = make_float2(acc[mt][nt][0], acc[mt][nt][1]);
                float2 v1 = make_float2(acc[mt][nt][2], acc[mt][nt][3]);
                *(float2*)(C + (size_t)r0 * N + col)       = v0;
                *(float2*)(C + (size_t)(r0 + 8) * N + col) = v1;
            }
        }
    }
}

// ---------------- conv(4) + SiLU: 8 timesteps per CTA (sliding window) -------
__global__ void __launch_bounds__(256)
conv_kernel(const float* __restrict__ conv_w, const float* __restrict__ conv_b)
{
    const int bl0 = blockIdx.x * 8;
    const int l0  = bl0 & (LSEQ - 1);
    const int tid = threadIdx.x;
    const float* base = g_zxbcdt + (size_t)bl0 * DPROJ + DIN;
    float* out = g_xc + (size_t)bl0 * CONVDIM;

    for (int c = tid; c < CONVDIM; c += 256) {
        const float4 w = *(const float4*)(conv_w + c * 4);
        const float bias = conv_b[c];
        float v[11];
#pragma unroll
        for (int k = 0; k < 11; k++) {
            const int ll = l0 + k - 3;
            v[k] = (ll >= 0) ? base[(ptrdiff_t)(k - 3) * DPROJ + c] : 0.f;
        }
#pragma unroll
        for (int j = 0; j < 8; j++) {
            const float a = bias + w.x * v[j] + w.y * v[j+1] + w.z * v[j+2] + w.w * v[j+3];
            out[(size_t)j * CONVDIM + c] = a / (1.f + expf(-a));
        }
    }
}

// ---------------- dt / dA ----------------
__global__ void __launch_bounds__(256)
dt_kernel(const float* __restrict__ dt_bias, const float* __restrict__ A_log)
{
    const int idx = blockIdx.x * 256 + threadIdx.x;
    const int bl = idx >> 5, hh = idx & 31;
    const float v = g_zxbcdt[(size_t)bl * DPROJ + (DPROJ - NH) + hh] + dt_bias[hh];
    const float dtv = (v > 20.f) ? v : log1pf(expf(v));
    g_dt[idx] = dtv;
    g_dA[idx] = expf(-expf(A_log[hh]) * dtv);
}

// ---------------- selective scan (R9 exact: 256 thr, 2p x 16n per thread) ----
#define SC_STAGES 4
#define SC_STEPS  4
__global__ void __launch_bounds__(256)
scan_kernel(const float* __restrict__ Dv)
{
    const int h = blockIdx.x, b = blockIdx.y;
    const int tid = threadIdx.x;
    const int nc = tid & 7;
    const int pg = tid >> 3;
    const int p0 = pg * 2;

    const float* xc  = g_xc + (size_t)b * LSEQ * CONVDIM;
    const float* dAp = g_dA + (size_t)b * LSEQ * NH + h;
    const float* dtp = g_dt + (size_t)b * LSEQ * NH + h;
    float* yout = g_y + (size_t)b * LSEQ * DIN + h * HD + p0;

    __shared__ __align__(16) float sB[SC_STAGES][SC_STEPS][160];
    __shared__ __align__(16) float sC[SC_STAGES][SC_STEPS][160];
    __shared__ __align__(16) float sx[SC_STAGES][SC_STEPS][64];
    __shared__ float sdA[SC_STAGES][SC_STEPS];
    __shared__ float sdt[SC_STAGES][SC_STEPS];

    auto load_stage = [&](int slot, int l0) {
#pragma unroll
        for (int pass = 0; pass < 2; pass++) {
            const int idx = tid + pass * 256;
            if (idx < 320) {
                const int j = idx / 80, op = idx % 80;
                const float* row = xc + (size_t)(l0 + j) * CONVDIM;
                if (op < 64) {
                    const int isC = op >> 5, o = op & 31;
                    const int chunk = o >> 2, q = o & 3;
                    const float* src = row + DIN + isC * DSTATE + chunk * 16 + q * 4;
                    float* dstf = (isC ? &sC[slot][j][0] : &sB[slot][j][0]) + chunk * 20 + q * 4;
                    cp16(smem_u32(dstf), src, 16);
                } else {
                    const int o = op - 64;
                    cp16(smem_u32(&sx[slot][j][o * 4]), row + h * HD + o * 4, 16);
                }
            } else if (idx < 328) {
                const int t = idx - 320, j = t >> 1;
                if (t & 1) cp4(smem_u32(&sdt[slot][j]), dtp + (size_t)(l0 + j) * NH);
                else       cp4(smem_u32(&sdA[slot][j]), dAp + (size_t)(l0 + j) * NH);
            }
        }
    };

    ull hs0[8], hs1[8];
#pragma unroll
    for (int i = 0; i < 8; i++) { hs0[i] = 0ull; hs1[i] = 0ull; }
    const float Dh = Dv[h];

#pragma unroll
    for (int s = 0; s < SC_STAGES; s++) { load_stage(s, SC_STEPS * s); cp_commit(); }

    const int niter = LSEQ / SC_STEPS;
    for (int it = 0; it < niter; it++) {
        const int slot = it & (SC_STAGES - 1);
        cp_wait<SC_STAGES - 1>();
        __syncthreads();

#pragma unroll
        for (int j = 0; j < SC_STEPS; j++) {
            const float dAv = sdA[slot][j];
            const float dtv = sdt[slot][j];
            const float2 xv = *(const float2*)&sx[slot][j][p0];
            const float s0 = dtv * xv.x, s1 = dtv * xv.y;
            const ull dA2 = pack2(dAv, dAv);
            const ull s20 = pack2(s0, s0);
            const ull s21 = pack2(s1, s1);

            const ulonglong2* B2 = (const ulonglong2*)(&sB[slot][j][nc * 20]);
            const ulonglong2* C2 = (const ulonglong2*)(&sC[slot][j][nc * 20]);
            ull acc0 = 0ull, acc1 = 0ull;
#pragma unroll
            for (int i = 0; i < 4; i++) {
                const ulonglong2 bb = B2[i], cc = C2[i];
                hs0[2*i]   = ffma2(dA2, hs0[2*i],   fmul2(s20, bb.x));
                acc0       = ffma2(hs0[2*i],   cc.x, acc0);
                hs1[2*i]   = ffma2(dA2, hs1[2*i],   fmul2(s21, bb.x));
                acc1       = ffma2(hs1[2*i],   cc.x, acc1);
                hs0[2*i+1] = ffma2(dA2, hs0[2*i+1], fmul2(s20, bb.y));
                acc0       = ffma2(hs0[2*i+1], cc.y, acc0);
                hs1[2*i+1] = ffma2(dA2, hs1[2*i+1], fmul2(s21, bb.y));
                acc1       = ffma2(hs1[2*i+1], cc.y, acc1);
            }
            const float2 f0 = unpack2(acc0), f1 = unpack2(acc1);
            float r0 = f0.x + f0.y;
            float r1 = f1.x + f1.y;
#pragma unroll
            for (int o = 1; o < 8; o <<= 1) {
                r0 += __shfl_xor_sync(0xffffffffu, r0, o);
                r1 += __shfl_xor_sync(0xffffffffu, r1, o);
            }
            if (nc == 0) {
                float2 ov;
                ov.x = r0 + Dh * xv.x;
                ov.y = r1 + Dh * xv.y;
                *(float2*)(yout + (size_t)(SC_STEPS * it + j) * DIN) = ov;
            }
        }
        __syncthreads();
        if (it + SC_STAGES < niter) load_stage(slot, SC_STEPS * (it + SC_STAGES));
        cp_commit();
    }
}

// ---------------- gating + RMSNorm -> fp16 ----------------
__global__ void __launch_bounds__(256)
gate_norm_kernel(const float* __restrict__ norm_w)
{
    const int bl = blockIdx.x;
    const float* yrow = g_y + (size_t)bl * DIN;
    const float* zrow = g_zxbcdt + (size_t)bl * DPROJ;
    __half* hrow = g_yh + (size_t)bl * DIN;
    const int tid = threadIdx.x;

    float v[8];
    float ss = 0.f;
#pragma unroll
    for (int j = 0; j < 8; j++) {
        const int c = tid + j * 256;
        const float z = zrow[c];
        const float val = yrow[c] * (z / (1.f + expf(-z)));
        v[j] = val;
        ss += val * val;
    }
#pragma unroll
    for (int o = 16; o; o >>= 1) ss += __shfl_xor_sync(0xffffffffu, ss, o);
    __shared__ float red[8];
    if ((tid & 31) == 0) red[tid >> 5] = ss;
    __syncthreads();
    float tot = 0.f;
#pragma unroll
    for (int i = 0; i < 8; i++) tot += red[i];
    const float scale = rsqrtf(tot * (1.f / (float)DIN) + 1e-5f);
#pragma unroll
    for (int j = 0; j < 8; j++) {
        const int c = tid + j * 256;
        hrow[c] = __float2half(v[j] * scale * norm_w[c]);
    }
}

// ---------------- launch ----------------
extern "C" void kernel_launch(void* const* d_in, const int* in_sizes, int n_in,
                              void* d_out, int out_size)
{
    (void)in_sizes; (void)n_in; (void)out_size;

    const float* hidden  = (const float*)d_in[0];
    const float* W_in    = (const float*)d_in[1];
    const float* conv_w  = (const float*)d_in[2];
    const float* conv_b  = (const float*)d_in[3];
    const float* dt_bias = (const float*)d_in[4];
    const float* A_log   = (const float*)d_in[5];
    const float* Dvec    = (const float*)d_in[6];
    const float* norm_w  = (const float*)d_in[7];
    const float* W_out   = (const float*)d_in[8];
    float* out = (float*)d_out;

    static float* zx = nullptr;
    static __half *ah, *w1h, *yh, *w2h;
    if (!zx) {
        void* p;
        cudaGetSymbolAddress(&p, g_zxbcdt); zx  = (float*)p;
        cudaGetSymbolAddress(&p, g_ah);   ah  = (__half*)p;
        cudaGetSymbolAddress(&p, g_w1h);  w1h = (__half*)p;
        cudaGetSymbolAddress(&p, g_yh);   yh  = (__half*)p;
        cudaGetSymbolAddress(&p, g_w2h);  w2h = (__half*)p;
        cudaFuncSetAttribute(gemm_hmma, cudaFuncAttributeMaxDynamicSharedMemorySize, GS_DYN);
    }

    // 0) operand prep (fp16)
    {
        const int n4 = MROWS * DMODEL / 4;
        convert_h<<<(n4 + 255) / 256, 256>>>(hidden, ah, n4);
    }
    transpose_h<<<dim3(DPROJ / 32, DMODEL / 32), 256>>>(W_in, w1h, DMODEL, DPROJ);
    transpose_h<<<dim3(DMODEL / 32, DIN / 32), 256>>>(W_out, w2h, DIN, DMODEL);

    // 1) zxbcdt = hidden @ W_in (fp16 single-pass HMMA, BK=64)
    gemm_hmma<<<dim3((DPROJ + 127) / 128, MROWS / 128), 256, GS_DYN>>>(
        ah, w1h, zx, DPROJ, DMODEL);

    // 2) conv + silu (8 steps/CTA) and dt/dA
    conv_kernel<<<MROWS / 8, 256>>>(conv_w, conv_b);
    dt_kernel<<<MROWS * NH / 256, 256>>>(dt_bias, A_log);

    // 3) selective scan (R9 exact)
    scan_kernel<<<dim3(NH, BB), 256>>>(Dvec);

    // 4) gating + rmsnorm -> fp16
    gate_norm_kernel<<<MROWS, 256>>>(norm_w);

    // 5) out = y @ W_out
    gemm_hmma<<<dim3(DMODEL / 128, MROWS / 128), 256, GS_DYN>>>(
        yh, w2h, out, DMODEL, DIN);
}